// round 14
// baseline (speedup 1.0000x reference)
#include <cuda_runtime.h>
#include <cstdint>

// Problem shape (fixed): T=8, B=32, C=128, H=32, W=32
// x_accum: [T,B,C,H,W] fp32 -> spikes [T,B,C,H,W] fp32 (LIF scan over T).
// Pure HBM streaming: 128 MiB in + 128 MiB out; measured mixed-stream ceiling
// ~5.8 TB/s => kernel floor ~37us. This round: persistent grid (1 wave, 592
// CTAs = 148 SMs x 4) to remove ~6 wave transitions + redundant CTA setup.

#define T_STEPS   8
#define VEC_PER_T 1048576u       // (32*128*32*32)/4 float4 per t-plane
#define EPS       1e-12f
#define NBLOCKS   592u           // 148 SMs * 4 CTAs/SM -> exactly one wave
#define NTHREADS  256u

__device__ __forceinline__ float decode_scalar_f(const void* p) {
    // tau may arrive as int32 or float32; decode defensively.
    int iv = *reinterpret_cast<const int*>(p);
    if (iv >= 1 && iv <= (1 << 23)) return (float)iv;   // plausible int32
    return __int_as_float(iv);                          // else raw float bits
}

__global__ void __launch_bounds__(NTHREADS, 4)   // ~56 regs: 8 LDG.128 in flight
integer_neuron_kernel(const float* __restrict__ x,
                      const float* __restrict__ prev_scale,
                      const float* __restrict__ prev_bias,
                      const float* __restrict__ vth,
                      const void* __restrict__ tau_p,
                      const int*  __restrict__ first_p,
                      float* __restrict__ out)
{
    // Loop-invariant scalars
    const float tau_f = decode_scalar_f(tau_p);
    const bool  first = (__ldg(first_p) != 0);
    const float vth0  = __ldg(vth);
    const float mul   = first ? 1.0f : tau_f;

    const float4* xp = reinterpret_cast<const float4*>(x);
    float4*       op = reinterpret_cast<float4*>(out);

    const unsigned stride = NBLOCKS * NTHREADS;           // 151552 float4 / chunk

    for (unsigned vec = blockIdx.x * NTHREADS + threadIdx.x;
         vec < VEC_PER_T; vec += stride)
    {
        // Channel constants (c uniform within a block: 256 thr * 4 = 1024 = H*W).
        // Recomputed per chunk (2 divides / 18KB of traffic: negligible).
        const int   c      = (int)((vec >> 8) & 127u);
        const float s_eps  = __fadd_rn(__ldg(prev_scale + c), EPS);
        const float bias_s = rintf(__fdiv_rn(__fmul_rn(__ldg(prev_bias + c), tau_f), s_eps));
        const float vth_s  = rintf(__fdiv_rn(__fmul_rn(vth0, tau_f), s_eps));
        const float nvth_s = -vth_s;

        // ---- all T loads up front, streaming (evict-first): 8x LDG.128.CS ----
        float4 xv[T_STEPS];
#pragma unroll
        for (int t = 0; t < T_STEPS; t++)
            xv[t] = __ldcs(xp + (size_t)t * VEC_PER_T + vec);

        float4 m = make_float4(0.f, 0.f, 0.f, 0.f);
#pragma unroll
        for (int t = 0; t < T_STEPS; t++) {
            float4 v = xv[t];
            // Bit-exact vs reference: mem = (mem + x_t*mul) + bias_scaled,
            // all rn, no FMA contraction across the adds.
            m.x = __fadd_rn(__fadd_rn(m.x, __fmul_rn(v.x, mul)), bias_s);
            m.y = __fadd_rn(__fadd_rn(m.y, __fmul_rn(v.y, mul)), bias_s);
            m.z = __fadd_rn(__fadd_rn(m.z, __fmul_rn(v.z, mul)), bias_s);
            m.w = __fadd_rn(__fadd_rn(m.w, __fmul_rn(v.w, mul)), bias_s);

            float4 spk;
            spk.x = (m.x >= vth_s) ? 1.0f : 0.0f;
            spk.y = (m.y >= vth_s) ? 1.0f : 0.0f;
            spk.z = (m.z >= vth_s) ? 1.0f : 0.0f;
            spk.w = (m.w >= vth_s) ? 1.0f : 0.0f;

            // soft reset: spk*vth_s is exact (0 or vth_s) => single-rounded FMA
            // is bit-identical to rn(m - spk*vth). Branch-free.
            m.x = __fmaf_rn(spk.x, nvth_s, m.x);
            m.y = __fmaf_rn(spk.y, nvth_s, m.y);
            m.z = __fmaf_rn(spk.z, nvth_s, m.z);
            m.w = __fmaf_rn(spk.w, nvth_s, m.w);

            __stcs(op + (size_t)t * VEC_PER_T + vec, spk);  // streaming store
        }
    }
}

extern "C" void kernel_launch(void* const* d_in, const int* in_sizes, int n_in,
                              void* d_out, int out_size)
{
    // metadata order: x_accum, prev_scale, prev_bias, vth, tau, is_first_layer
    const float* x     = (const float*)d_in[0];
    const float* scale = (const float*)d_in[1];
    const float* bias  = (const float*)d_in[2];
    const float* vth   = (const float*)d_in[3];
    const void*  tau   = d_in[4];
    const int*   first = (const int*)d_in[5];
    float* out = (float*)d_out;

    (void)in_sizes; (void)n_in; (void)out_size;

    integer_neuron_kernel<<<NBLOCKS, NTHREADS>>>(x, scale, bias, vth, tau, first, out);
}

// round 16
// speedup vs baseline: 1.0755x; 1.0755x over previous
#include <cuda_runtime.h>
#include <cstdint>

// Problem shape (fixed): T=8, B=32, C=128, H=32, W=32
// x_accum: [T,B,C,H,W] fp32 -> spikes [T,B,C,H,W] fp32 (LIF scan over T).
// Pure HBM streaming: 128 MiB in + 128 MiB out (compulsory).
// Measured mixed R/W ceiling ~5.8 TB/s => kernel floor ~37us.
//
// Config rationale (from R4/R12/R14 ncu evidence): high occupancy (regs~32,
// occ ~84%) beats deep per-thread MLP (regs 56, occ 42%) and persistent grids
// for achieved DRAM%. One CTA per 1024-element channel plane, one wave per
// kernel epoch, hardware handles wave overlap.

#define T_STEPS   8
#define VEC_PER_T 1048576u       // (32*128*32*32)/4 float4 per t-plane
#define EPS       1e-12f

__device__ __forceinline__ float decode_scalar_f(const void* p) {
    // tau may arrive as int32 or float32; decode defensively.
    int iv = *reinterpret_cast<const int*>(p);
    if (iv >= 1 && iv <= (1 << 23)) return (float)iv;   // plausible int32
    return __int_as_float(iv);                          // else raw float bits
}

__global__ void __launch_bounds__(256)     // no minBlocks: let ptxas pick ~32 regs -> occ ~84%
integer_neuron_kernel(const float* __restrict__ x,
                      const float* __restrict__ prev_scale,
                      const float* __restrict__ prev_bias,
                      const float* __restrict__ vth,
                      const void* __restrict__ tau_p,
                      const int*  __restrict__ first_p,
                      float* __restrict__ out)
{
    const unsigned vec = blockIdx.x * 256u + threadIdx.x;   // float4 index in one t-plane

    // Channel constants (c uniform per block: 256 thr * 4 elem = 1024 = H*W).
    const int   c      = (int)((vec >> 8) & 127u);
    const float tau_f  = decode_scalar_f(tau_p);
    const bool  first  = (__ldg(first_p) != 0);
    const float s_eps  = __fadd_rn(__ldg(prev_scale + c), EPS);
    const float bias_s = rintf(__fdiv_rn(__fmul_rn(__ldg(prev_bias + c), tau_f), s_eps));
    const float vth_s  = rintf(__fdiv_rn(__fmul_rn(__ldg(vth),           tau_f), s_eps));
    const float nvth_s = -vth_s;
    const float mul    = first ? 1.0f : tau_f;

    const float4* xp = reinterpret_cast<const float4*>(x) + vec;
    float4*       op = reinterpret_cast<float4*>(out) + vec;

    // Hoisted loads (ptxas will schedule load-use pairs at 32 regs; with
    // occ ~84% the aggregate in-flight bytes saturate regardless).
    float4 xv[T_STEPS];
#pragma unroll
    for (int t = 0; t < T_STEPS; t++)
        xv[t] = xp[(size_t)t * VEC_PER_T];

    float4 m = make_float4(0.f, 0.f, 0.f, 0.f);
#pragma unroll
    for (int t = 0; t < T_STEPS; t++) {
        float4 v = xv[t];
        // Bit-exact vs reference: mem = (mem + x_t*mul) + bias_scaled,
        // all rn, no FMA contraction across the adds.
        m.x = __fadd_rn(__fadd_rn(m.x, __fmul_rn(v.x, mul)), bias_s);
        m.y = __fadd_rn(__fadd_rn(m.y, __fmul_rn(v.y, mul)), bias_s);
        m.z = __fadd_rn(__fadd_rn(m.z, __fmul_rn(v.z, mul)), bias_s);
        m.w = __fadd_rn(__fadd_rn(m.w, __fmul_rn(v.w, mul)), bias_s);

        float4 spk;
        spk.x = (m.x >= vth_s) ? 1.0f : 0.0f;
        spk.y = (m.y >= vth_s) ? 1.0f : 0.0f;
        spk.z = (m.z >= vth_s) ? 1.0f : 0.0f;
        spk.w = (m.w >= vth_s) ? 1.0f : 0.0f;

        // soft reset: spk*vth_s is exact (0 or vth_s) => single-rounded FMA
        // is bit-identical to rn(m - spk*vth). Branch-free.
        m.x = __fmaf_rn(spk.x, nvth_s, m.x);
        m.y = __fmaf_rn(spk.y, nvth_s, m.y);
        m.z = __fmaf_rn(spk.z, nvth_s, m.z);
        m.w = __fmaf_rn(spk.w, nvth_s, m.w);

        op[(size_t)t * VEC_PER_T] = spk;
    }
}

extern "C" void kernel_launch(void* const* d_in, const int* in_sizes, int n_in,
                              void* d_out, int out_size)
{
    // metadata order: x_accum, prev_scale, prev_bias, vth, tau, is_first_layer
    const float* x     = (const float*)d_in[0];
    const float* scale = (const float*)d_in[1];
    const float* bias  = (const float*)d_in[2];
    const float* vth   = (const float*)d_in[3];
    const void*  tau   = d_in[4];
    const int*   first = (const int*)d_in[5];
    float* out = (float*)d_out;

    (void)in_sizes; (void)n_in; (void)out_size;

    integer_neuron_kernel<<<VEC_PER_T / 256u, 256>>>(x, scale, bias, vth, tau, first, out);
}